// round 6
// baseline (speedup 1.0000x reference)
#include <cuda_runtime.h>
#include <cstdint>

// ---------------------------------------------------------------------------
// ConvKanModel, dense FFMA2 (fp32x2 packed pipe) direct conv, v2 blocking.
// Thread = 16 pixels x 8 out channels (64 packed f32x2 accumulators).
// Per (j,tap): 4 broadcast LDS64 weights (reused over 16 px) + 16 LDS32 act
// (each act value serves 8 outch via packed broadcast) -> 0.75 B per lane-MAC,
// under the 128B/cyc crossbar; fma-pipe-bound at the FFMA2 2x datapath.
// ---------------------------------------------------------------------------

#define NB      4
#define CCH     16
#define HW      512
#define PLANE   (HW*HW)
#define TOTAL   (NB*CCH*PLANE)

#define TILE    32
#define HALO    34
#define HALO2   (HALO*HALO)       // 1156
#define PL      1160              // feature-plane stride (words)
#define NWW     1728              // 12 feat * 9 tap * 16 outch
#define W_W     (12*PL)           // 13920
#define SMEM_WORDS (W_W + NWW)    // 15648
#define SMEM_BYTES (SMEM_WORDS*4) // 62592

__device__ float g_z1[TOTAL];
__device__ float g_z2[TOTAL];
__device__ float g_m1[64], g_r1[64], g_m2[64], g_r2[64];
__device__ float g_Wp[2*CCH*NWW];   // pre-formatted weights [layer][c][(j*9+tap)*16+o]

typedef unsigned long long u64;

__device__ __forceinline__ u64 pack2(float x) {
    u64 r;
    asm("mov.b64 %0, {%1, %1};" : "=l"(r) : "f"(x));
    return r;
}
__device__ __forceinline__ void fma2(u64& d, u64 a, u64 b) {
    asm("fma.rn.f32x2 %0, %1, %2, %0;" : "+l"(d) : "l"(a), "l"(b));
}

// ---- weight prep: layout [(j*9 + ky*3 + kx)*16 + o] per (layer, channel) ---
__global__ void prep_W(const float* __restrict__ bw1, const float* __restrict__ sw1,
                       const float* __restrict__ bw2, const float* __restrict__ sw2)
{
    const int l = blockIdx.x >> 4, c = blockIdx.x & 15;
    const float* bw = l ? bw2 : bw1;
    const float* sw = l ? sw2 : sw1;
    float* dst = g_Wp + (size_t)(l*CCH + c) * NWW;
    for (int e = threadIdx.x; e < NWW; e += blockDim.x) {
        const int o    = e & 15;
        const int rest = e >> 4;          // 0..107
        const int kx   = rest % 3;
        const int ky   = (rest / 3) % 3;
        const int j    = rest / 9;        // 0..11
        float v;
        if (j == 0) v = bw[((o*CCH + c)*3 + ky)*3 + kx];
        else        v = sw[((o*(CCH*11) + c*11 + (j-1))*3 + ky)*3 + kx];
        dst[(j*9 + ky*3 + kx)*16 + o] = v;
    }
}

// ---------------------------------------------------------------------------
// Fused KAN conv. Block: 128 threads, 32x32 tile, 16 out channels.
// tid: col = tid&31, wq = tid>>5: rowg = (wq&1)*16, ohalf = wq>>1.
// ---------------------------------------------------------------------------
template<bool NORM>
__global__ __launch_bounds__(128, 2)
void conv_v2(const float* __restrict__ in,
             const float* __restrict__ gW,      // this layer's g_Wp slice
             const float* __restrict__ mean,
             const float* __restrict__ rstd,
             const float* __restrict__ alpha_p,
             float* __restrict__ out)
{
    extern __shared__ uint32_t sm[];
    float* s_act = reinterpret_cast<float*>(sm);
    float* s_w   = reinterpret_cast<float*>(sm) + W_W;

    const int tid   = threadIdx.x;
    const int col   = tid & 31;
    const int wq    = tid >> 5;
    const int rowg  = (wq & 1) * 16;
    const int ohalf = wq >> 1;
    const int bx    = blockIdx.x * TILE;
    const int by    = blockIdx.y * TILE;
    const int b     = blockIdx.z;

    const float alpha = NORM ? alpha_p[0] : 0.0f;

    u64 acc[16][4];
#pragma unroll
    for (int r = 0; r < 16; ++r)
#pragma unroll
        for (int p = 0; p < 4; ++p) acc[r][p] = 0ull;

    for (int c = 0; c < CCH; ++c) {
        __syncthreads();   // protect previous iteration's smem reads

        // ---- copy pre-formatted weights (uint4, L2-resident) ----
        {
            const uint4* gw4 = reinterpret_cast<const uint4*>(gW + (size_t)c * NWW);
            uint4* sw4 = reinterpret_cast<uint4*>(s_w);
#pragma unroll
            for (int i = 0; i < 4; ++i) {
                const int e = tid + i*128;
                if (e < NWW/4) sw4[e] = gw4[e];
            }
        }

        // ---- stage activation features for channel c ----
        const float* inp = in + (((size_t)(b*CCH + c)) << 18);
        float mu = 0.0f, rs = 0.0f;
        if (NORM) { mu = mean[b*CCH + c]; rs = rstd[b*CCH + c]; }

#pragma unroll
        for (int it = 0; it < 10; ++it) {
            const int idx = tid + it*128;
            if (idx >= HALO2) break;
            const int iy = idx / HALO;
            const int ix = idx - iy * HALO;
            const int gy = by + iy - 1;
            const int gx = bx + ix - 1;

            float a0 = 0.0f, w0 = 0.0f, w1 = 0.0f, w2 = 0.0f, w3 = 0.0f;
            int cell = -100;
            if (gy >= 0 && gy < HW && gx >= 0 && gx < HW) {
                float x = inp[gy*HW + gx];
                if (NORM) {
                    x = (x - mu) * rs;
                    x = (x < 0.0f) ? alpha * x : x;        // prelu
                }
                a0 = x / (1.0f + __expf(-x));              // silu
                const float u  = (x + 1.75f) * 4.0f;
                const float cf = floorf(u);
                const int   ci = (int)cf;
                if (ci >= 0 && ci < 14) {
                    cell = ci;
                    const float t = u - cf, mt = 1.0f - t, t2 = t*t, t3 = t2*t;
                    w0 = mt*mt*mt * (1.0f/6.0f);
                    w1 = (3.0f*t3 - 6.0f*t2 + 4.0f) * (1.0f/6.0f);
                    w2 = (-3.0f*t3 + 3.0f*t2 + 3.0f*t + 1.0f) * (1.0f/6.0f);
                    w3 = t3 * (1.0f/6.0f);
                }
            }
            s_act[idx] = a0;                               // feature 0 = silu
#pragma unroll
            for (int j = 1; j < 12; ++j) s_act[j*PL + idx] = 0.0f;
            if (cell >= 0) {
                // stored bases 0..10 live in slots j = basis+1
                if (cell >= 3)               s_act[(cell-2)*PL + idx] = w0;
                if (cell >= 2 && cell <= 12) s_act[(cell-1)*PL + idx] = w1;
                if (cell >= 1 && cell <= 11) s_act[(cell  )*PL + idx] = w2;
                if (cell <= 10)              s_act[(cell+1)*PL + idx] = w3;
            }
        }
        __syncthreads();

        // ---- accumulate: 12 features x 9 taps ----
        for (int j = 0; j < 12; ++j) {
            const float* actp = s_act + j*PL;
            const float* wjp  = s_w + j*144 + ohalf*8;
            for (int ky = 0; ky < 3; ++ky) {
                const float* arow0 = actp + (rowg + ky)*HALO + col;
#pragma unroll
                for (int kx = 0; kx < 3; ++kx) {
                    const u64* wp = reinterpret_cast<const u64*>(wjp + (ky*3 + kx)*16);
                    const u64 wv0 = wp[0], wv1 = wp[1], wv2 = wp[2], wv3 = wp[3];
                    const float* ar = arow0 + kx;
#pragma unroll
                    for (int r = 0; r < 16; ++r) {
                        const u64 a2 = pack2(ar[r*HALO]);
                        fma2(acc[r][0], a2, wv0);
                        fma2(acc[r][1], a2, wv1);
                        fma2(acc[r][2], a2, wv2);
                        fma2(acc[r][3], a2, wv3);
                    }
                }
            }
        }
    }

    // ---- epilogue: 16 pixels x 8 out channels ----
#pragma unroll
    for (int p = 0; p < 4; ++p) {
        const int o0 = ohalf*8 + 2*p;
        float* op0 = out + (((size_t)(b*CCH + o0    )) << 18);
        float* op1 = out + (((size_t)(b*CCH + o0 + 1)) << 18);
#pragma unroll
        for (int r = 0; r < 16; ++r) {
            const int gy = by + rowg + r;
            const uint32_t lo = (uint32_t)(acc[r][p] & 0xffffffffull);
            const uint32_t hi = (uint32_t)(acc[r][p] >> 32);
            op0[gy*HW + bx + col] = __uint_as_float(lo);
            op1[gy*HW + bx + col] = __uint_as_float(hi);
        }
    }
}

// ---------------------------------------------------------------------------
__global__ void stats_kernel(const float* __restrict__ z,
                             float* __restrict__ mean, float* __restrict__ rstd)
{
    __shared__ float sh_s[1024], sh_q[1024];
    const int bc = blockIdx.x;
    const float4* p = reinterpret_cast<const float4*>(z + (size_t)bc * PLANE);
    float s = 0.0f, q = 0.0f;
    for (int i = threadIdx.x; i < PLANE/4; i += 1024) {
        const float4 v = p[i];
        s += v.x + v.y + v.z + v.w;
        q += v.x*v.x + v.y*v.y + v.z*v.z + v.w*v.w;
    }
    sh_s[threadIdx.x] = s; sh_q[threadIdx.x] = q;
    __syncthreads();
    for (int off = 512; off > 0; off >>= 1) {
        if (threadIdx.x < off) {
            sh_s[threadIdx.x] += sh_s[threadIdx.x + off];
            sh_q[threadIdx.x] += sh_q[threadIdx.x + off];
        }
        __syncthreads();
    }
    if (threadIdx.x == 0) {
        const float m = sh_s[0] * (1.0f/PLANE);
        const float v = sh_q[0] * (1.0f/PLANE) - m*m;
        mean[bc] = m; rstd[bc] = rsqrtf(v + 1e-5f);
    }
}

__global__ void finalize_kernel(const float* __restrict__ z,
                                const float* __restrict__ mean,
                                const float* __restrict__ rstd,
                                const float* __restrict__ alpha_p,
                                float* __restrict__ out)
{
    const size_t i4 = (size_t)blockIdx.x * blockDim.x + threadIdx.x;
    if (i4 >= TOTAL/4) return;
    const int bc = (int)(i4 >> 16);
    const float alpha = alpha_p[0], m = mean[bc], rs = rstd[bc];
    float4 v = reinterpret_cast<const float4*>(z)[i4];
    float* vp = &v.x;
#pragma unroll
    for (int k = 0; k < 4; ++k) {
        float t = (vp[k] - m) * rs;
        t = (t < 0.0f) ? alpha * t : t;
        vp[k] = 1.0f / (1.0f + __expf(-t));
    }
    reinterpret_cast<float4*>(out)[i4] = v;
}

// ---------------------------------------------------------------------------
extern "C" void kernel_launch(void* const* d_in, const int* in_sizes, int n_in,
                              void* d_out, int out_size)
{
    const float* x   = (const float*)d_in[0];
    const float* bw1 = (const float*)d_in[1];
    const float* sw1 = (const float*)d_in[2];
    const float* a1  = (const float*)d_in[3];
    const float* bw2 = (const float*)d_in[4];
    const float* sw2 = (const float*)d_in[5];
    const float* a2  = (const float*)d_in[6];
    float* out = (float*)d_out;

    float *z1, *z2, *m1, *r1, *m2, *r2, *Wp;
    cudaGetSymbolAddress((void**)&z1, g_z1);
    cudaGetSymbolAddress((void**)&z2, g_z2);
    cudaGetSymbolAddress((void**)&m1, g_m1);
    cudaGetSymbolAddress((void**)&r1, g_r1);
    cudaGetSymbolAddress((void**)&m2, g_m2);
    cudaGetSymbolAddress((void**)&r2, g_r2);
    cudaGetSymbolAddress((void**)&Wp, g_Wp);

    cudaFuncSetAttribute(conv_v2<false>,
                         cudaFuncAttributeMaxDynamicSharedMemorySize, SMEM_BYTES);
    cudaFuncSetAttribute(conv_v2<true>,
                         cudaFuncAttributeMaxDynamicSharedMemorySize, SMEM_BYTES);

    prep_W<<<32, 128>>>(bw1, sw1, bw2, sw2);

    const dim3 grid(HW/TILE, HW/TILE, NB);   // 16 x 16 x 4

    conv_v2<false><<<grid, 128, SMEM_BYTES>>>(
        x, Wp, nullptr, nullptr, nullptr, z1);
    stats_kernel<<<NB*CCH, 1024>>>(z1, m1, r1);

    conv_v2<true><<<grid, 128, SMEM_BYTES>>>(
        z1, Wp + (size_t)CCH*NWW, m1, r1, a1, z2);
    stats_kernel<<<NB*CCH, 1024>>>(z2, m2, r2);

    finalize_kernel<<<(TOTAL/4 + 255)/256, 256>>>(z2, m2, r2, a2, out);
}

// round 7
// speedup vs baseline: 1.0390x; 1.0390x over previous
#include <cuda_runtime.h>
#include <cstdint>

// ---------------------------------------------------------------------------
// ConvKanModel via Winograd F(2x2,3x3) + packed FFMA2 GEMM.
// Per layer: z = base_conv(silu(x)) + spline_conv(bases(x)); inst-norm+prelu
// folded into next layer's staging / final kernel.
// Winograd: per 16x16 output tile, 8x8 patches; 192 input planes (12 feat x
// 16 ch, channel-serial k=12 per iteration); per transform point pt (16):
//   M[64 tiles][16 o] += V[64][k] * U[k][16 o]
// with f32x2 packed accumulators over output-channel pairs.
// ---------------------------------------------------------------------------

#define NB      4
#define CCH     16
#define HW      512
#define PLANE   (HW*HW)
#define TOTAL   (NB*CCH*PLANE)

#define OT      16               // output tile (px)
#define HLO     18               // input halo
#define HLO2    324
#define FPL     325              // feature plane stride (words)
#define NT      64               // winograd tiles per block (8x8)
#define VTP     68               // V tile-dim padded stride
#define VPT     (12*VTP)         // V per-pt stride = 816
#define UPT     200              // U per-pt stride (padded from 192)

// smem word offsets
#define W_FEAT  0                        // [12][325] = 3900
#define W_V     3900                     // [16][12][68] = 13056 (M overlays)
#define W_U     16956                    // [16][200] = 3200
#define SMEM_WORDS 20156
#define SMEM_BYTES (SMEM_WORDS*4)        // 80624

__device__ float g_z1[TOTAL];
__device__ float g_z2[TOTAL];
__device__ float g_m1[64], g_r1[64], g_m2[64], g_r2[64];
__device__ float g_U[2*CCH*3072];        // [layer][c][pt(16)][j(12)][o(16)]

typedef unsigned long long u64;

__device__ __forceinline__ u64 pack2(float x) {
    u64 r;
    asm("mov.b64 %0, {%1, %1};" : "=l"(r) : "f"(x));
    return r;
}
__device__ __forceinline__ void fma2(u64& d, u64 a, u64 b) {
    asm("fma.rn.f32x2 %0, %1, %2, %0;" : "+l"(d) : "l"(a), "l"(b));
}
__device__ __forceinline__ float u64lo(u64 v) {
    return __uint_as_float((uint32_t)(v & 0xffffffffull));
}
__device__ __forceinline__ float u64hi(u64 v) {
    return __uint_as_float((uint32_t)(v >> 32));
}

// ---- weight pre-transform: U = G w G^T, layout [pt][j][o] per (l,c) -------
__global__ void prep_U(const float* __restrict__ bw1, const float* __restrict__ sw1,
                       const float* __restrict__ bw2, const float* __restrict__ sw2)
{
    const int l = blockIdx.x >> 4, c = blockIdx.x & 15;
    const float* bw = l ? bw2 : bw1;
    const float* sw = l ? sw2 : sw1;
    float* dst = g_U + (size_t)(l*CCH + c) * 3072;
    for (int e = threadIdx.x; e < 192; e += blockDim.x) {
        const int j = e >> 4, o = e & 15;
        float g[3][3];
#pragma unroll
        for (int ky = 0; ky < 3; ++ky)
#pragma unroll
            for (int kx = 0; kx < 3; ++kx)
                g[ky][kx] = (j == 0)
                    ? bw[((o*CCH + c)*3 + ky)*3 + kx]
                    : sw[((o*(CCH*11) + c*11 + (j-1))*3 + ky)*3 + kx];
        // t = G g  (4x3)
        float t[4][3];
#pragma unroll
        for (int k = 0; k < 3; ++k) {
            t[0][k] = g[0][k];
            t[1][k] = 0.5f*(g[0][k] + g[1][k] + g[2][k]);
            t[2][k] = 0.5f*(g[0][k] - g[1][k] + g[2][k]);
            t[3][k] = g[2][k];
        }
        // U = t G^T (4x4)
#pragma unroll
        for (int r = 0; r < 4; ++r) {
            float u0 = t[r][0];
            float u1 = 0.5f*(t[r][0] + t[r][1] + t[r][2]);
            float u2 = 0.5f*(t[r][0] - t[r][1] + t[r][2]);
            float u3 = t[r][2];
            dst[((r*4 + 0)*12 + j)*16 + o] = u0;
            dst[((r*4 + 1)*12 + j)*16 + o] = u1;
            dst[((r*4 + 2)*12 + j)*16 + o] = u2;
            dst[((r*4 + 3)*12 + j)*16 + o] = u3;
        }
    }
}

// ---------------------------------------------------------------------------
// Winograd KAN conv. Block: 256 threads; output tile 16x16 px, 16 out ch.
// GEMM role: pt = tid>>4 (0..15), tg = tid&15 -> tiles 4tg..4tg+3.
// acc[tile][opair] u64 = 32 u64 = 64 regs.
// ---------------------------------------------------------------------------
template<bool NORM>
__global__ __launch_bounds__(256, 2)
void conv_wino(const float* __restrict__ in,
               const float* __restrict__ gU,     // this layer's g_U slice
               const float* __restrict__ mean,
               const float* __restrict__ rstd,
               const float* __restrict__ alpha_p,
               float* __restrict__ out)
{
    extern __shared__ uint32_t sm[];
    float* s_feat = reinterpret_cast<float*>(sm);          // [12][325]
    float* s_V    = reinterpret_cast<float*>(sm) + W_V;    // [16][12][68]
    float* s_U    = reinterpret_cast<float*>(sm) + W_U;    // [16][200]
    float* s_M    = s_V;                                   // overlay [64][8][17]

    const int tid = threadIdx.x;
    const int pt  = tid >> 4;
    const int tg  = tid & 15;
    const int bx  = blockIdx.x * OT;
    const int by  = blockIdx.y * OT;
    const int b   = blockIdx.z;

    const float alpha = NORM ? alpha_p[0] : 0.0f;

    u64 acc[4][8];
#pragma unroll
    for (int t = 0; t < 4; ++t)
#pragma unroll
        for (int p = 0; p < 8; ++p) acc[t][p] = 0ull;

    for (int c = 0; c < CCH; ++c) {
        __syncthreads();   // protect previous iteration's smem reads

        // ---- stage U for channel c: [pt][j*16+o] with pt stride 200 ----
        {
            const float* gUc = gU + (size_t)c * 3072;
            for (int w = tid; w < 3072; w += 256) {
                const int p_ = w / 192;
                s_U[p_*UPT + (w - p_*192)] = gUc[w];
            }
        }

        // ---- stage 12 feature planes over the 18x18 halo ----
        const float* inp = in + (((size_t)(b*CCH + c)) << 18);
        float mu = 0.0f, rs = 0.0f;
        if (NORM) { mu = mean[b*CCH + c]; rs = rstd[b*CCH + c]; }

        for (int idx = tid; idx < HLO2; idx += 256) {
            const int iy = idx / HLO;
            const int ix = idx - iy * HLO;
            const int gy = by + iy - 1;
            const int gx = bx + ix - 1;

            float a0 = 0.0f, w0 = 0.0f, w1 = 0.0f, w2 = 0.0f, w3 = 0.0f;
            int cell = -100;
            if (gy >= 0 && gy < HW && gx >= 0 && gx < HW) {
                float x = inp[gy*HW + gx];
                if (NORM) {
                    x = (x - mu) * rs;
                    x = (x < 0.0f) ? alpha * x : x;        // prelu
                }
                a0 = x / (1.0f + __expf(-x));              // silu
                const float u  = (x + 1.75f) * 4.0f;
                const float cf = floorf(u);
                const int   ci = (int)cf;
                if (ci >= 0 && ci < 14) {
                    cell = ci;
                    const float t = u - cf, mt = 1.0f - t, t2 = t*t, t3 = t2*t;
                    w0 = mt*mt*mt * (1.0f/6.0f);
                    w1 = (3.0f*t3 - 6.0f*t2 + 4.0f) * (1.0f/6.0f);
                    w2 = (-3.0f*t3 + 3.0f*t2 + 3.0f*t + 1.0f) * (1.0f/6.0f);
                    w3 = t3 * (1.0f/6.0f);
                }
            }
            s_feat[idx] = a0;                              // feature 0 = silu
#pragma unroll
            for (int j = 1; j < 12; ++j) s_feat[j*FPL + idx] = 0.0f;
            if (cell >= 0) {
                if (cell >= 3)               s_feat[(cell-2)*FPL + idx] = w0;
                if (cell >= 2 && cell <= 12) s_feat[(cell-1)*FPL + idx] = w1;
                if (cell >= 1 && cell <= 11) s_feat[(cell  )*FPL + idx] = w2;
                if (cell <= 10)              s_feat[(cell+1)*FPL + idx] = w3;
            }
        }
        __syncthreads();

        // ---- input transforms: 768 jobs = 64 patches x 12 planes ----
        for (int jid = tid; jid < 768; jid += 256) {
            const int patch = jid & 63;
            const int j     = jid >> 6;
            const int py = patch >> 3, px = patch & 7;
            const float* dp = s_feat + j*FPL + (py*2)*HLO + px*2;

            float d[4][4];
#pragma unroll
            for (int r = 0; r < 4; ++r)
#pragma unroll
                for (int q = 0; q < 4; ++q) d[r][q] = dp[r*HLO + q];

            // w = B^T d  (rows)
            float wr[4][4];
#pragma unroll
            for (int q = 0; q < 4; ++q) {
                wr[0][q] = d[0][q] - d[2][q];
                wr[1][q] = d[1][q] + d[2][q];
                wr[2][q] = d[2][q] - d[1][q];
                wr[3][q] = d[1][q] - d[3][q];
            }
            // V = w B  (cols)
            float* vb = s_V + j*VTP + patch;
#pragma unroll
            for (int r = 0; r < 4; ++r) {
                vb[(r*4 + 0)*VPT] = wr[r][0] - wr[r][2];
                vb[(r*4 + 1)*VPT] = wr[r][1] + wr[r][2];
                vb[(r*4 + 2)*VPT] = wr[r][2] - wr[r][1];
                vb[(r*4 + 3)*VPT] = wr[r][1] - wr[r][3];
            }
        }
        __syncthreads();

        // ---- GEMM: acc[4 tiles][16 o] += V[4t][k] * U[k][16 o], k=0..11 ----
        {
            const float* Vp = s_V + pt*VPT + 4*tg;
            const float* Up = s_U + pt*UPT;
#pragma unroll
            for (int k = 0; k < 12; ++k) {
                const float4 v = *reinterpret_cast<const float4*>(Vp + k*VTP);
                const u64* up = reinterpret_cast<const u64*>(Up + k*16);
                u64 u0 = up[0], u1 = up[1], u2 = up[2], u3 = up[3];
                u64 u4 = up[4], u5 = up[5], u6 = up[6], u7 = up[7];
                const u64 p0 = pack2(v.x), p1 = pack2(v.y);
                const u64 p2 = pack2(v.z), p3 = pack2(v.w);
                fma2(acc[0][0], p0, u0); fma2(acc[0][1], p0, u1);
                fma2(acc[0][2], p0, u2); fma2(acc[0][3], p0, u3);
                fma2(acc[0][4], p0, u4); fma2(acc[0][5], p0, u5);
                fma2(acc[0][6], p0, u6); fma2(acc[0][7], p0, u7);
                fma2(acc[1][0], p1, u0); fma2(acc[1][1], p1, u1);
                fma2(acc[1][2], p1, u2); fma2(acc[1][3], p1, u3);
                fma2(acc[1][4], p1, u4); fma2(acc[1][5], p1, u5);
                fma2(acc[1][6], p1, u6); fma2(acc[1][7], p1, u7);
                fma2(acc[2][0], p2, u0); fma2(acc[2][1], p2, u1);
                fma2(acc[2][2], p2, u2); fma2(acc[2][3], p2, u3);
                fma2(acc[2][4], p2, u4); fma2(acc[2][5], p2, u5);
                fma2(acc[2][6], p2, u6); fma2(acc[2][7], p2, u7);
                fma2(acc[3][0], p3, u0); fma2(acc[3][1], p3, u1);
                fma2(acc[3][2], p3, u2); fma2(acc[3][3], p3, u3);
                fma2(acc[3][4], p3, u4); fma2(acc[3][5], p3, u5);
                fma2(acc[3][6], p3, u6); fma2(acc[3][7], p3, u7);
            }
        }
    }

    // ---- epilogue: inverse transform, 2 oc-halves through smem ----
#pragma unroll 1
    for (int h = 0; h < 2; ++h) {
        __syncthreads();   // protect s_V (h=0) / previous inverse reads (h=1)
        // write M[tile][oo][pt] for o in [8h, 8h+8)
#pragma unroll
        for (int t = 0; t < 4; ++t)
#pragma unroll
            for (int q = 0; q < 4; ++q) {
                const u64 a = acc[t][h*4 + q];
                float* mp = s_M + ((4*tg + t)*8 + 2*q)*17 + pt;
                mp[0]  = u64lo(a);
                mp[17] = u64hi(a);
            }
        __syncthreads();
        // inverse: 512 jobs = 64 tiles x 8 oo
        for (int jid = tid; jid < 512; jid += 256) {
            const int tile = jid >> 3, oo = jid & 7;
            const int o = h*8 + oo;
            const float* mp = s_M + (tile*8 + oo)*17;
            float m[16];
#pragma unroll
            for (int i = 0; i < 16; ++i) m[i] = mp[i];
            // t = A^T M  (2x4)
            float t0[4], t1[4];
#pragma unroll
            for (int q = 0; q < 4; ++q) {
                t0[q] = m[q] + m[4+q] + m[8+q];
                t1[q] = m[4+q] - m[8+q] - m[12+q];
            }
            const float y00 = t0[0] + t0[1] + t0[2];
            const float y01 = t0[1] - t0[2] - t0[3];
            const float y10 = t1[0] + t1[1] + t1[2];
            const float y11 = t1[1] - t1[2] - t1[3];

            const int ty = tile >> 3, tx = tile & 7;
            const int gy = by + ty*2, gx = bx + tx*2;
            float* op = out + (((size_t)(b*CCH + o)) << 18);
            op[(size_t)gy*HW + gx]       = y00;
            op[(size_t)gy*HW + gx + 1]   = y01;
            op[(size_t)(gy+1)*HW + gx]   = y10;
            op[(size_t)(gy+1)*HW + gx+1] = y11;
        }
    }
}

// ---------------------------------------------------------------------------
__global__ void stats_kernel(const float* __restrict__ z,
                             float* __restrict__ mean, float* __restrict__ rstd)
{
    __shared__ float sh_s[1024], sh_q[1024];
    const int bc = blockIdx.x;
    const float4* p = reinterpret_cast<const float4*>(z + (size_t)bc * PLANE);
    float s = 0.0f, q = 0.0f;
    for (int i = threadIdx.x; i < PLANE/4; i += 1024) {
        const float4 v = p[i];
        s += v.x + v.y + v.z + v.w;
        q += v.x*v.x + v.y*v.y + v.z*v.z + v.w*v.w;
    }
    sh_s[threadIdx.x] = s; sh_q[threadIdx.x] = q;
    __syncthreads();
    for (int off = 512; off > 0; off >>= 1) {
        if (threadIdx.x < off) {
            sh_s[threadIdx.x] += sh_s[threadIdx.x + off];
            sh_q[threadIdx.x] += sh_q[threadIdx.x + off];
        }
        __syncthreads();
    }
    if (threadIdx.x == 0) {
        const float m = sh_s[0] * (1.0f/PLANE);
        const float v = sh_q[0] * (1.0f/PLANE) - m*m;
        mean[bc] = m; rstd[bc] = rsqrtf(v + 1e-5f);
    }
}

__global__ void finalize_kernel(const float* __restrict__ z,
                                const float* __restrict__ mean,
                                const float* __restrict__ rstd,
                                const float* __restrict__ alpha_p,
                                float* __restrict__ out)
{
    const size_t i4 = (size_t)blockIdx.x * blockDim.x + threadIdx.x;
    if (i4 >= TOTAL/4) return;
    const int bc = (int)(i4 >> 16);
    const float alpha = alpha_p[0], m = mean[bc], rs = rstd[bc];
    float4 v = reinterpret_cast<const float4*>(z)[i4];
    float* vp = &v.x;
#pragma unroll
    for (int k = 0; k < 4; ++k) {
        float t = (vp[k] - m) * rs;
        t = (t < 0.0f) ? alpha * t : t;
        vp[k] = 1.0f / (1.0f + __expf(-t));
    }
    reinterpret_cast<float4*>(out)[i4] = v;
}

// ---------------------------------------------------------------------------
extern "C" void kernel_launch(void* const* d_in, const int* in_sizes, int n_in,
                              void* d_out, int out_size)
{
    const float* x   = (const float*)d_in[0];
    const float* bw1 = (const float*)d_in[1];
    const float* sw1 = (const float*)d_in[2];
    const float* a1  = (const float*)d_in[3];
    const float* bw2 = (const float*)d_in[4];
    const float* sw2 = (const float*)d_in[5];
    const float* a2  = (const float*)d_in[6];
    float* out = (float*)d_out;

    float *z1, *z2, *m1, *r1, *m2, *r2, *U;
    cudaGetSymbolAddress((void**)&z1, g_z1);
    cudaGetSymbolAddress((void**)&z2, g_z2);
    cudaGetSymbolAddress((void**)&m1, g_m1);
    cudaGetSymbolAddress((void**)&r1, g_r1);
    cudaGetSymbolAddress((void**)&m2, g_m2);
    cudaGetSymbolAddress((void**)&r2, g_r2);
    cudaGetSymbolAddress((void**)&U,  g_U);

    cudaFuncSetAttribute(conv_wino<false>,
                         cudaFuncAttributeMaxDynamicSharedMemorySize, SMEM_BYTES);
    cudaFuncSetAttribute(conv_wino<true>,
                         cudaFuncAttributeMaxDynamicSharedMemorySize, SMEM_BYTES);

    prep_U<<<32, 192>>>(bw1, sw1, bw2, sw2);

    const dim3 grid(HW/OT, HW/OT, NB);   // 32 x 32 x 4 = 4096 blocks

    conv_wino<false><<<grid, 256, SMEM_BYTES>>>(
        x, U, nullptr, nullptr, nullptr, z1);
    stats_kernel<<<NB*CCH, 1024>>>(z1, m1, r1);

    conv_wino<true><<<grid, 256, SMEM_BYTES>>>(
        z1, U + (size_t)CCH*3072, m1, r1, a1, z2);
    stats_kernel<<<NB*CCH, 1024>>>(z2, m2, r2);

    finalize_kernel<<<(TOTAL/4 + 255)/256, 256>>>(z2, m2, r2, a2, out);
}